// round 6
// baseline (speedup 1.0000x reference)
#include <cuda_runtime.h>

#define Nn 50000
#define Ee 800000
#define ETOT (Ee + Nn)
#define Dd 128
#define Hh 8
#define Cc 16
#define Ll 3
#define SCAN_NB ((Nn + 255) / 256)   // 196 blocks

// -------- scratch (device globals: no allocation allowed) --------
__device__ __align__(256) float g_xl[Nn * Dd];
__device__ __align__(256) float g_xr[Nn * Dd];
__device__ int g_deg[Nn];
__device__ int g_indptr[Nn + 1];
__device__ int g_cursor[Nn];
__device__ int g_src[ETOT];
__device__ int g_bsum[SCAN_NB];
__device__ int g_bbase[SCAN_NB];

typedef unsigned long long u64;

__device__ __forceinline__ u64 pk2(float lo, float hi) {
    u64 r; asm("mov.b64 %0, {%1,%2};" : "=l"(r) : "f"(lo), "f"(hi)); return r;
}
__device__ __forceinline__ void upk2(u64 v, float& lo, float& hi) {
    asm("mov.b64 {%0,%1}, %2;" : "=f"(lo), "=f"(hi) : "l"(v));
}
__device__ __forceinline__ void fma2(u64& d, u64 a, u64 b) {
    asm("fma.rn.f32x2 %0, %1, %2, %0;" : "+l"(d) : "l"(a), "l"(b));
}
__device__ __forceinline__ float lrelu(float v) { return v > 0.f ? v : 0.2f * v; }

// -------- setup kernels --------
__global__ void k_copy(const float* __restrict__ x, float* __restrict__ out) {
    int i = blockIdx.x * blockDim.x + threadIdx.x;
    if (i < Nn * Dd / 4) ((float4*)out)[i] = ((const float4*)x)[i];
}

__global__ void k_zero() {
    int i = blockIdx.x * blockDim.x + threadIdx.x;
    if (i < Nn) g_deg[i] = 0;
}

__global__ void k_hist(const int* __restrict__ ei) {
    int e = blockIdx.x * blockDim.x + threadIdx.x;
    if (e < Ee) atomicAdd(&g_deg[ei[Ee + e]], 1);
}

// ---- hierarchical scan over (deg[i] + 1) ----
__global__ void k_part() {
    __shared__ int sp[256];
    int t = threadIdx.x;
    int idx = blockIdx.x * 256 + t;
    int v = (idx < Nn) ? g_deg[idx] + 1 : 0;
    sp[t] = v;
    __syncthreads();
#pragma unroll
    for (int off = 128; off; off >>= 1) {
        if (t < off) sp[t] += sp[t + off];
        __syncthreads();
    }
    if (t == 0) g_bsum[blockIdx.x] = sp[0];
}

__global__ void k_scanb() {
    __shared__ int sp[256];
    int t = threadIdx.x;
    int v = (t < SCAN_NB) ? g_bsum[t] : 0;
    sp[t] = v;
    __syncthreads();
#pragma unroll
    for (int off = 1; off < 256; off <<= 1) {
        int u = (t >= off) ? sp[t - off] : 0;
        __syncthreads();
        sp[t] += u;
        __syncthreads();
    }
    if (t < SCAN_NB) g_bbase[t] = sp[t] - v;   // exclusive
}

__global__ void k_fill() {
    __shared__ int sp[256];
    int t = threadIdx.x;
    int idx = blockIdx.x * 256 + t;
    int v = (idx < Nn) ? g_deg[idx] + 1 : 0;
    sp[t] = v;
    __syncthreads();
#pragma unroll
    for (int off = 1; off < 256; off <<= 1) {
        int u = (t >= off) ? sp[t - off] : 0;
        __syncthreads();
        sp[t] += u;
        __syncthreads();
    }
    int off0 = g_bbase[blockIdx.x] + sp[t] - v;  // exclusive prefix
    if (idx < Nn) {
        g_indptr[idx] = off0;
        g_cursor[idx] = off0;
        if (idx == Nn - 1) g_indptr[Nn] = off0 + v;
    }
}

__global__ void k_scatter(const int* __restrict__ ei) {
    int e = blockIdx.x * blockDim.x + threadIdx.x;
    if (e >= ETOT) return;
    int s, d;
    if (e < Ee) { s = ei[e]; d = ei[Ee + e]; }
    else { s = e - Ee; d = s; }
    int pos = atomicAdd(&g_cursor[d], 1);
    g_src[pos] = s;
}

// -------- GEMM: out[M,128] = h[M,128] @ W[128,128], packed f32x2 FMA --------
__global__ void __launch_bounds__(256) k_gemm(const float* __restrict__ hbuf,
                                              const float* __restrict__ Wlp,
                                              const float* __restrict__ Wrp) {
    __shared__ float sA[64][132];
    const float* W = (blockIdx.y == 0) ? Wlp : Wrp;
    float* out = (blockIdx.y == 0) ? g_xl : g_xr;
    int tid = threadIdx.x;
    int row0 = blockIdx.x * 64;
    for (int t = tid; t < 64 * 32; t += 256) {
        int r = t >> 5, c = t & 31;
        float4 v = make_float4(0.f, 0.f, 0.f, 0.f);
        if (row0 + r < Nn) v = *(const float4*)(hbuf + (row0 + r) * Dd + c * 4);
        *(float4*)(&sA[r][c * 4]) = v;
    }
    __syncthreads();
    int tx = tid & 15;
    int ty = tid >> 4;
    u64 acc[4][4];
#pragma unroll
    for (int i = 0; i < 4; i++)
#pragma unroll
        for (int j = 0; j < 4; j++) acc[i][j] = 0ull;
    const float4* Wv = (const float4*)W;
#pragma unroll 8
    for (int k = 0; k < 128; k++) {
        float4 b0 = __ldg(&Wv[k * 32 + tx * 2]);
        float4 b1 = __ldg(&Wv[k * 32 + tx * 2 + 1]);
        u64 bb0 = pk2(b0.x, b0.y), bb1 = pk2(b0.z, b0.w);
        u64 bb2 = pk2(b1.x, b1.y), bb3 = pk2(b1.z, b1.w);
#pragma unroll
        for (int i = 0; i < 4; i++) {
            float a = sA[ty * 4 + i][k];
            u64 aa = pk2(a, a);
            fma2(acc[i][0], aa, bb0);
            fma2(acc[i][1], aa, bb1);
            fma2(acc[i][2], aa, bb2);
            fma2(acc[i][3], aa, bb3);
        }
    }
#pragma unroll
    for (int i = 0; i < 4; i++) {
        int r = row0 + ty * 4 + i;
        if (r < Nn) {
            float4 o0, o1;
            upk2(acc[i][0], o0.x, o0.y); upk2(acc[i][1], o0.z, o0.w);
            upk2(acc[i][2], o1.x, o1.y); upk2(acc[i][3], o1.z, o1.w);
            *(float4*)(out + r * Dd + tx * 8) = o0;
            *(float4*)(out + r * Dd + tx * 8 + 4) = o1;
        }
    }
}

// -------- fused GATv2 layer: 4-stream pipelined online softmax + LN + ELU + residual
// one warp per node; lane owns 4 channels, head = lane/4 (4 lanes per head).
__global__ void __launch_bounds__(256) k_gat(const float* __restrict__ att,
                                             const float* __restrict__ bias,
                                             const float* __restrict__ gamma,
                                             const float* __restrict__ beta,
                                             float* __restrict__ hbuf) {
    int node = (blockIdx.x * blockDim.x + threadIdx.x) >> 5;
    if (node >= Nn) return;
    int lane = threadIdx.x & 31;
    float4 xrv = *(const float4*)(g_xr + node * Dd + lane * 4);
    float4 atv = __ldg((const float4*)att + lane);
    int beg = g_indptr[node];
    int end = g_indptr[node + 1];

    // 4 independent online-softmax streams
    float m[4], s[4];
    float ax[4], ay[4], az[4], aw[4];
#pragma unroll
    for (int j = 0; j < 4; j++) {
        m[j] = -1e30f; s[j] = 0.f;
        ax[j] = 0.f; ay[j] = 0.f; az[j] = 0.f; aw[j] = 0.f;
    }

    float4 cur[4];
#pragma unroll
    for (int j = 0; j < 4; j++) {
        cur[j] = make_float4(0, 0, 0, 0);
        if (beg + j < end) {
            int sc = g_src[beg + j];
            cur[j] = *(const float4*)(g_xl + sc * Dd + lane * 4);
        }
    }

    for (int p = beg; p < end; p += 4) {
        // prefetch next chunk (4 independent loads in flight)
        float4 nxt[4];
#pragma unroll
        for (int j = 0; j < 4; j++) {
            nxt[j] = cur[j];
            if (p + 4 + j < end) {
                int sc = g_src[p + 4 + j];
                nxt[j] = *(const float4*)(g_xl + sc * Dd + lane * 4);
            }
        }
        // process current chunk: 4 independent chains (shuffles/MUFUs overlap)
#pragma unroll
        for (int j = 0; j < 4; j++) {
            if (p + j < end) {
                float4 c = cur[j];
                float t = lrelu(c.x + xrv.x) * atv.x + lrelu(c.y + xrv.y) * atv.y +
                          lrelu(c.z + xrv.z) * atv.z + lrelu(c.w + xrv.w) * atv.w;
                t += __shfl_xor_sync(0xffffffffu, t, 1);
                t += __shfl_xor_sync(0xffffffffu, t, 2);
                float mn = fmaxf(m[j], t);
                float sc = __expf(m[j] - mn);
                float w = __expf(t - mn);
                s[j] = s[j] * sc + w;
                ax[j] = fmaf(ax[j], sc, w * c.x);
                ay[j] = fmaf(ay[j], sc, w * c.y);
                az[j] = fmaf(az[j], sc, w * c.z);
                aw[j] = fmaf(aw[j], sc, w * c.w);
                m[j] = mn;
            }
        }
#pragma unroll
        for (int j = 0; j < 4; j++) cur[j] = nxt[j];
    }

    // merge 4 streams (empty streams have m=-1e30 -> weight 0)
    float mm = fmaxf(fmaxf(m[0], m[1]), fmaxf(m[2], m[3]));
    float S = 0.f, AX = 0.f, AY = 0.f, AZ = 0.f, AW = 0.f;
#pragma unroll
    for (int j = 0; j < 4; j++) {
        float wj = __expf(m[j] - mm);
        S = fmaf(s[j], wj, S);
        AX = fmaf(ax[j], wj, AX);
        AY = fmaf(ay[j], wj, AY);
        AZ = fmaf(az[j], wj, AZ);
        AW = fmaf(aw[j], wj, AW);
    }

    float inv = 1.f / S;
    float4 bv = __ldg((const float4*)bias + lane);
    float ox = fmaf(AX, inv, bv.x);
    float oy = fmaf(AY, inv, bv.y);
    float oz = fmaf(AZ, inv, bv.z);
    float ow = fmaf(AW, inv, bv.w);
    // LayerNorm over 128 channels (warp allreduce)
    float sum = ox + oy + oz + ow;
#pragma unroll
    for (int off = 16; off; off >>= 1) sum += __shfl_xor_sync(0xffffffffu, sum, off);
    float mu = sum * (1.f / 128.f);
    float dx = ox - mu, dy = oy - mu, dz = oz - mu, dw = ow - mu;
    float ss = dx * dx + dy * dy + dz * dz + dw * dw;
#pragma unroll
    for (int off = 16; off; off >>= 1) ss += __shfl_xor_sync(0xffffffffu, ss, off);
    float rstd = rsqrtf(ss * (1.f / 128.f) + 1e-5f);
    float4 gv = __ldg((const float4*)gamma + lane);
    float4 btv = __ldg((const float4*)beta + lane);
    float y0 = fmaf(dx * rstd, gv.x, btv.x);
    float y1 = fmaf(dy * rstd, gv.y, btv.y);
    float y2 = fmaf(dz * rstd, gv.z, btv.z);
    float y3 = fmaf(dw * rstd, gv.w, btv.w);
    float e0 = y0 > 0.f ? y0 : (__expf(y0) - 1.f);
    float e1 = y1 > 0.f ? y1 : (__expf(y1) - 1.f);
    float e2 = y2 > 0.f ? y2 : (__expf(y2) - 1.f);
    float e3 = y3 > 0.f ? y3 : (__expf(y3) - 1.f);
    float4 hv = *(const float4*)(hbuf + node * Dd + lane * 4);
    hv.x += e0; hv.y += e1; hv.z += e2; hv.w += e3;
    *(float4*)(hbuf + node * Dd + lane * 4) = hv;
}

extern "C" void kernel_launch(void* const* d_in, const int* in_sizes, int n_in,
                              void* d_out, int out_size) {
    const float* x     = (const float*)d_in[0];
    const float* Wl    = (const float*)d_in[1];
    const float* Wr    = (const float*)d_in[2];
    const float* att   = (const float*)d_in[3];
    const float* bias  = (const float*)d_in[4];
    const float* gamma = (const float*)d_in[5];
    const float* beta  = (const float*)d_in[6];
    const int*   ei    = (const int*)d_in[7];
    float* h = (float*)d_out;

    dim3 ggrid((Nn + 63) / 64, 2);

    k_copy<<<(Nn * Dd / 4 + 255) / 256, 256>>>(x, h);
    k_zero<<<(Nn + 255) / 256, 256>>>();
    k_hist<<<(Ee + 255) / 256, 256>>>(ei);
    // layer-0 GEMM moved up (only needs h) so it lands in ncu's profiled slot
    k_gemm<<<ggrid, 256>>>(h, Wl, Wr);
    k_part<<<SCAN_NB, 256>>>();
    k_scanb<<<1, 256>>>();
    k_fill<<<SCAN_NB, 256>>>();
    k_scatter<<<(ETOT + 255) / 256, 256>>>(ei);

    k_gat<<<(Nn + 7) / 8, 256>>>(att, bias, gamma, beta, h);
    for (int l = 1; l < Ll; l++) {
        k_gemm<<<ggrid, 256>>>(h, Wl + l * Dd * Dd, Wr + l * Dd * Dd);
        k_gat<<<(Nn + 7) / 8, 256>>>(att + l * Hh * Cc, bias + l * Dd,
                                     gamma + l * Dd, beta + l * Dd, h);
    }
}

// round 8
// speedup vs baseline: 1.4001x; 1.4001x over previous
#include <cuda_runtime.h>

#define Nn 50000
#define Ee 800000
#define ETOT (Ee + Nn)
#define Dd 128
#define Hh 8
#define Cc 16
#define Ll 3
#define SCAN_NB ((Nn + 255) / 256)   // 196 blocks
#define KC 32

// -------- scratch (device globals: no allocation allowed) --------
__device__ __align__(256) float g_xl[Nn * Dd];
__device__ __align__(256) float g_xr[Nn * Dd];
__device__ int g_deg[Nn];
__device__ int g_indptr[Nn + 1];
__device__ int g_cursor[Nn];
__device__ int g_src[ETOT];
__device__ int g_bsum[SCAN_NB];
__device__ int g_bbase[SCAN_NB];

typedef unsigned long long u64;

__device__ __forceinline__ u64 pk2(float lo, float hi) {
    u64 r; asm("mov.b64 %0, {%1,%2};" : "=l"(r) : "f"(lo), "f"(hi)); return r;
}
__device__ __forceinline__ void upk2(u64 v, float& lo, float& hi) {
    asm("mov.b64 {%0,%1}, %2;" : "=f"(lo), "=f"(hi) : "l"(v));
}
__device__ __forceinline__ void fma2(u64& d, u64 a, u64 b) {
    asm("fma.rn.f32x2 %0, %1, %2, %0;" : "+l"(d) : "l"(a), "l"(b));
}
__device__ __forceinline__ float lrelu(float v) { return v > 0.f ? v : 0.2f * v; }

// -------- setup kernels --------
__global__ void k_copy(const float* __restrict__ x, float* __restrict__ out) {
    int i = blockIdx.x * blockDim.x + threadIdx.x;
    if (i < Nn * Dd / 4) ((float4*)out)[i] = ((const float4*)x)[i];
}

__global__ void k_zero() {
    int i = blockIdx.x * blockDim.x + threadIdx.x;
    if (i < Nn) g_deg[i] = 0;
}

__global__ void k_hist(const int* __restrict__ ei) {
    int e = blockIdx.x * blockDim.x + threadIdx.x;
    if (e < Ee) atomicAdd(&g_deg[ei[Ee + e]], 1);
}

// ---- hierarchical scan over (deg[i] + 1) ----
__global__ void k_part() {
    __shared__ int sp[256];
    int t = threadIdx.x;
    int idx = blockIdx.x * 256 + t;
    int v = (idx < Nn) ? g_deg[idx] + 1 : 0;
    sp[t] = v;
    __syncthreads();
#pragma unroll
    for (int off = 128; off; off >>= 1) {
        if (t < off) sp[t] += sp[t + off];
        __syncthreads();
    }
    if (t == 0) g_bsum[blockIdx.x] = sp[0];
}

__global__ void k_scanb() {
    __shared__ int sp[256];
    int t = threadIdx.x;
    int v = (t < SCAN_NB) ? g_bsum[t] : 0;
    sp[t] = v;
    __syncthreads();
#pragma unroll
    for (int off = 1; off < 256; off <<= 1) {
        int u = (t >= off) ? sp[t - off] : 0;
        __syncthreads();
        sp[t] += u;
        __syncthreads();
    }
    if (t < SCAN_NB) g_bbase[t] = sp[t] - v;   // exclusive
}

__global__ void k_fill() {
    __shared__ int sp[256];
    int t = threadIdx.x;
    int idx = blockIdx.x * 256 + t;
    int v = (idx < Nn) ? g_deg[idx] + 1 : 0;
    sp[t] = v;
    __syncthreads();
#pragma unroll
    for (int off = 1; off < 256; off <<= 1) {
        int u = (t >= off) ? sp[t - off] : 0;
        __syncthreads();
        sp[t] += u;
        __syncthreads();
    }
    int off0 = g_bbase[blockIdx.x] + sp[t] - v;  // exclusive prefix
    if (idx < Nn) {
        g_indptr[idx] = off0;
        g_cursor[idx] = off0;
        if (idx == Nn - 1) g_indptr[Nn] = off0 + v;
    }
}

__global__ void k_scatter(const int* __restrict__ ei) {
    int e = blockIdx.x * blockDim.x + threadIdx.x;
    if (e >= ETOT) return;
    int s, d;
    if (e < Ee) { s = ei[e]; d = ei[Ee + e]; }
    else { s = e - Ee; d = s; }
    int pos = atomicAdd(&g_cursor[d], 1);
    g_src[pos] = s;
}

// -------- GEMM: out[M,128] = h[M,128] @ W[128,128]  (smem-tiled, f32x2 FMA)
// 128-row x 128-col tile per block, K chunked by 32; 8x8 per-thread microtile.
__global__ void __launch_bounds__(256, 2) k_gemm(const float* __restrict__ hbuf,
                                                 const float* __restrict__ Wlp,
                                                 const float* __restrict__ Wrp) {
    __shared__ float sA[128][KC + 4];
    __shared__ float sW[KC][132];
    const float* W = (blockIdx.y == 0) ? Wlp : Wrp;
    float* out = (blockIdx.y == 0) ? g_xl : g_xr;
    int tid = threadIdx.x;
    int row0 = blockIdx.x * 128;
    int tx = tid & 15;   // col block: tx*8
    int ty = tid >> 4;   // row block: ty*8
    u64 acc[8][4];
#pragma unroll
    for (int i = 0; i < 8; i++)
#pragma unroll
        for (int j = 0; j < 4; j++) acc[i][j] = 0ull;

    for (int kc = 0; kc < Dd; kc += KC) {
        // stage A chunk: rows [row0, row0+128), k [kc, kc+32) — 4 float4/thread
        {
            int c4 = tid & 7;     // float4 within chunk row
            int r = tid >> 3;     // 0..31
#pragma unroll
            for (int i = 0; i < 4; i++) {
                int row = r + i * 32;
                float4 v = make_float4(0.f, 0.f, 0.f, 0.f);
                if (row0 + row < Nn)
                    v = *(const float4*)(hbuf + (row0 + row) * Dd + kc + c4 * 4);
                *(float4*)(&sA[row][c4 * 4]) = v;
            }
        }
        // stage W chunk: k rows [kc, kc+32), all 128 cols — 4 float4/thread
        {
            int c4 = tid & 31;    // float4 col 0..31
            int kr = tid >> 5;    // 0..7
#pragma unroll
            for (int i = 0; i < 4; i++) {
                int k = kr + i * 8;
                float4 v = *(const float4*)(W + (kc + k) * Dd + c4 * 4);
                *(float4*)(&sW[k][c4 * 4]) = v;
            }
        }
        __syncthreads();
#pragma unroll
        for (int k = 0; k < KC; k++) {
            float4 b0 = *(const float4*)(&sW[k][tx * 8]);
            float4 b1 = *(const float4*)(&sW[k][tx * 8 + 4]);
            u64 bb0 = pk2(b0.x, b0.y), bb1 = pk2(b0.z, b0.w);
            u64 bb2 = pk2(b1.x, b1.y), bb3 = pk2(b1.z, b1.w);
#pragma unroll
            for (int i = 0; i < 8; i++) {
                float a = sA[ty * 8 + i][k];
                u64 aa = pk2(a, a);
                fma2(acc[i][0], aa, bb0);
                fma2(acc[i][1], aa, bb1);
                fma2(acc[i][2], aa, bb2);
                fma2(acc[i][3], aa, bb3);
            }
        }
        __syncthreads();
    }
#pragma unroll
    for (int i = 0; i < 8; i++) {
        int r = row0 + ty * 8 + i;
        if (r < Nn) {
            float4 o0, o1;
            upk2(acc[i][0], o0.x, o0.y); upk2(acc[i][1], o0.z, o0.w);
            upk2(acc[i][2], o1.x, o1.y); upk2(acc[i][3], o1.z, o1.w);
            *(float4*)(out + r * Dd + tx * 8) = o0;
            *(float4*)(out + r * Dd + tx * 8 + 4) = o1;
        }
    }
}

// -------- fused GATv2 layer: 2-stream online softmax + aggregate + LN + ELU + residual
// one warp per node; lane owns 4 channels, head = lane/4 (4 lanes per head).
__global__ void __launch_bounds__(256) k_gat(const float* __restrict__ att,
                                             const float* __restrict__ bias,
                                             const float* __restrict__ gamma,
                                             const float* __restrict__ beta,
                                             float* __restrict__ hbuf) {
    int node = (blockIdx.x * blockDim.x + threadIdx.x) >> 5;
    if (node >= Nn) return;
    int lane = threadIdx.x & 31;
    float4 xrv = *(const float4*)(g_xr + node * Dd + lane * 4);
    float4 atv = __ldg((const float4*)att + lane);
    int beg = g_indptr[node];
    int end = g_indptr[node + 1];

    float m0 = -1e30f, s0 = 0.f, a0x = 0.f, a0y = 0.f, a0z = 0.f, a0w = 0.f;
    float m1 = -1e30f, s1 = 0.f, a1x = 0.f, a1y = 0.f, a1z = 0.f, a1w = 0.f;

    float4 c0 = make_float4(0, 0, 0, 0), c1 = make_float4(0, 0, 0, 0);
    {
        int sa = g_src[beg];
        c0 = *(const float4*)(g_xl + sa * Dd + lane * 4);
        if (beg + 1 < end) {
            int sb = g_src[beg + 1];
            c1 = *(const float4*)(g_xl + sb * Dd + lane * 4);
        }
    }
    for (int p = beg; p < end; p += 2) {
        float4 n0 = c0, n1 = c1;
        if (p + 2 < end) {
            int sa = g_src[p + 2];
            n0 = *(const float4*)(g_xl + sa * Dd + lane * 4);
            if (p + 3 < end) {
                int sb = g_src[p + 3];
                n1 = *(const float4*)(g_xl + sb * Dd + lane * 4);
            }
        }
        {
            float t = lrelu(c0.x + xrv.x) * atv.x + lrelu(c0.y + xrv.y) * atv.y +
                      lrelu(c0.z + xrv.z) * atv.z + lrelu(c0.w + xrv.w) * atv.w;
            t += __shfl_xor_sync(0xffffffffu, t, 1);
            t += __shfl_xor_sync(0xffffffffu, t, 2);
            float mn = fmaxf(m0, t);
            float sc = __expf(m0 - mn);
            float w = __expf(t - mn);
            s0 = s0 * sc + w;
            a0x = fmaf(a0x, sc, w * c0.x);
            a0y = fmaf(a0y, sc, w * c0.y);
            a0z = fmaf(a0z, sc, w * c0.z);
            a0w = fmaf(a0w, sc, w * c0.w);
            m0 = mn;
        }
        if (p + 1 < end) {
            float t = lrelu(c1.x + xrv.x) * atv.x + lrelu(c1.y + xrv.y) * atv.y +
                      lrelu(c1.z + xrv.z) * atv.z + lrelu(c1.w + xrv.w) * atv.w;
            t += __shfl_xor_sync(0xffffffffu, t, 1);
            t += __shfl_xor_sync(0xffffffffu, t, 2);
            float mn = fmaxf(m1, t);
            float sc = __expf(m1 - mn);
            float w = __expf(t - mn);
            s1 = s1 * sc + w;
            a1x = fmaf(a1x, sc, w * c1.x);
            a1y = fmaf(a1y, sc, w * c1.y);
            a1z = fmaf(a1z, sc, w * c1.z);
            a1w = fmaf(a1w, sc, w * c1.w);
            m1 = mn;
        }
        c0 = n0; c1 = n1;
    }
    float mm = fmaxf(m0, m1);
    float e0s = __expf(m0 - mm), e1s = __expf(m1 - mm);
    float s = s0 * e0s + s1 * e1s;
    float ax = a0x * e0s + a1x * e1s;
    float ay = a0y * e0s + a1y * e1s;
    float az = a0z * e0s + a1z * e1s;
    float aw = a0w * e0s + a1w * e1s;

    float inv = 1.f / s;
    float4 bv = __ldg((const float4*)bias + lane);
    float ox = fmaf(ax, inv, bv.x);
    float oy = fmaf(ay, inv, bv.y);
    float oz = fmaf(az, inv, bv.z);
    float ow = fmaf(aw, inv, bv.w);
    float sum = ox + oy + oz + ow;
#pragma unroll
    for (int off = 16; off; off >>= 1) sum += __shfl_xor_sync(0xffffffffu, sum, off);
    float mu = sum * (1.f / 128.f);
    float dx = ox - mu, dy = oy - mu, dz = oz - mu, dw = ow - mu;
    float ss = dx * dx + dy * dy + dz * dz + dw * dw;
#pragma unroll
    for (int off = 16; off; off >>= 1) ss += __shfl_xor_sync(0xffffffffu, ss, off);
    float rstd = rsqrtf(ss * (1.f / 128.f) + 1e-5f);
    float4 gv = __ldg((const float4*)gamma + lane);
    float4 btv = __ldg((const float4*)beta + lane);
    float y0 = fmaf(dx * rstd, gv.x, btv.x);
    float y1 = fmaf(dy * rstd, gv.y, btv.y);
    float y2 = fmaf(dz * rstd, gv.z, btv.z);
    float y3 = fmaf(dw * rstd, gv.w, btv.w);
    float e0 = y0 > 0.f ? y0 : (__expf(y0) - 1.f);
    float e1 = y1 > 0.f ? y1 : (__expf(y1) - 1.f);
    float e2 = y2 > 0.f ? y2 : (__expf(y2) - 1.f);
    float e3 = y3 > 0.f ? y3 : (__expf(y3) - 1.f);
    float4 hv = *(const float4*)(hbuf + node * Dd + lane * 4);
    hv.x += e0; hv.y += e1; hv.z += e2; hv.w += e3;
    *(float4*)(hbuf + node * Dd + lane * 4) = hv;
}

extern "C" void kernel_launch(void* const* d_in, const int* in_sizes, int n_in,
                              void* d_out, int out_size) {
    const float* x     = (const float*)d_in[0];
    const float* Wl    = (const float*)d_in[1];
    const float* Wr    = (const float*)d_in[2];
    const float* att   = (const float*)d_in[3];
    const float* bias  = (const float*)d_in[4];
    const float* gamma = (const float*)d_in[5];
    const float* beta  = (const float*)d_in[6];
    const int*   ei    = (const int*)d_in[7];
    float* h = (float*)d_out;

    dim3 ggrid((Nn + 127) / 128, 2);

    k_copy<<<(Nn * Dd / 4 + 255) / 256, 256>>>(x, h);
    k_zero<<<(Nn + 255) / 256, 256>>>();
    k_hist<<<(Ee + 255) / 256, 256>>>(ei);
    // layer-0 GEMM early (only needs h) so it lands in ncu's profiled slot
    k_gemm<<<ggrid, 256>>>(h, Wl, Wr);
    k_part<<<SCAN_NB, 256>>>();
    k_scanb<<<1, 256>>>();
    k_fill<<<SCAN_NB, 256>>>();
    k_scatter<<<(ETOT + 255) / 256, 256>>>(ei);

    k_gat<<<(Nn + 7) / 8, 256>>>(att, bias, gamma, beta, h);
    for (int l = 1; l < Ll; l++) {
        k_gemm<<<ggrid, 256>>>(h, Wl + l * Dd * Dd, Wr + l * Dd * Dd);
        k_gat<<<(Nn + 7) / 8, 256>>>(att + l * Hh * Cc, bias + l * Dd,
                                     gamma + l * Dd, beta + l * Dd, h);
    }
}